// round 1
// baseline (speedup 1.0000x reference)
#include <cuda_runtime.h>
#include <cuda_bf16.h>
#include <cstdint>

// ---------------------------------------------------------------------------
// ModulatedConv (StyleGAN2 modconv + conv_transpose2d stride2 + 4x4 FIR)
// Decomposition:
//   1) prep:  wm = w*gain*(style+1); d = rsqrt(sum wm^2 + eps); Wmod = wm*d
//             stored as [b][tap][o][i]   (tap = kh*3+kw)
//   2) gemm:  Ytap[b][tap][o][h*32+w] = sum_i Wmod[b][tap][o][i] * x[b][i][h*32+w]
//             72 GEMMs of M=512, N=1024, K=512   (pure GEMM, no im2col)
//   3) fir:   y1[s,t] = sum_{kh,kw: s=2h+kh,t=2w+kw} Ytap[kh][kw][h][w]
//             y2[p,q] = sum_{u,v} f[u,v] y1[p-1+u,q-1+v]
//             collapsed via c1[e][d][kh] = f1[2d+kh-e+1]/4, f1={.25,.75,.75,.25}
// ---------------------------------------------------------------------------

#define Bsz   8
#define CI    512
#define CO    512
#define HW    1024   // 32*32
#define NTAP  9

// scratch (device globals; no runtime allocation allowed)
__device__ float g_wmod[(size_t)Bsz * NTAP * CO * CI];   // 75.5 MB
__device__ float g_ytap[(size_t)Bsz * NTAP * CO * HW];   // 151 MB

// ------------------------------ helpers -----------------------------------
__device__ __forceinline__ unsigned long long pk2(float x, float y) {
    unsigned long long r;
    asm("mov.b64 %0, {%1,%2};" : "=l"(r) : "f"(x), "f"(y));
    return r;
}
__device__ __forceinline__ float2 unpk2(unsigned long long v) {
    float2 r;
    asm("mov.b64 {%0,%1}, %2;" : "=f"(r.x), "=f"(r.y) : "l"(v));
    return r;
}
__device__ __forceinline__ void fma2(unsigned long long& d,
                                     unsigned long long a,
                                     unsigned long long b) {
    asm("fma.rn.f32x2 %0, %1, %2, %0;" : "+l"(d) : "l"(a), "l"(b));
}

// ------------------------------ 1) prep -----------------------------------
// grid: (CO, Bsz), block: 256
__global__ void __launch_bounds__(256) prep_kernel(const float* __restrict__ w,
                                                   const float* __restrict__ styles) {
    const int o = blockIdx.x;
    const int b = blockIdx.y;
    const float gain = 1.0f / 1536.0f;  // 1/sqrt(512*512*9)

    __shared__ float swm[CI * NTAP];    // 18 KB, [i][tap] order (matches w layout)
    __shared__ float red[8];
    __shared__ float s_d;

    const float* wo = w + (size_t)o * (CI * NTAP);
    const float* st = styles + (size_t)b * CI;

    float lsum = 0.f;
    for (int idx = threadIdx.x; idx < CI * NTAP; idx += 256) {
        int i = idx / 9;
        float v = wo[idx] * gain * (st[i] + 1.0f);
        swm[idx] = v;
        lsum += v * v;
    }
    // block reduce
    #pragma unroll
    for (int off = 16; off; off >>= 1)
        lsum += __shfl_down_sync(0xffffffffu, lsum, off);
    if ((threadIdx.x & 31) == 0) red[threadIdx.x >> 5] = lsum;
    __syncthreads();
    if (threadIdx.x == 0) {
        float t = 0.f;
        #pragma unroll
        for (int k = 0; k < 8; k++) t += red[k];
        s_d = rsqrtf(t + 1e-8f);
    }
    __syncthreads();
    const float d = s_d;

    // write [b][tap][o][i] with i contiguous (coalesced)
    for (int idx = threadIdx.x; idx < CI * NTAP; idx += 256) {
        int tap = idx >> 9;          // 0..8
        int i   = idx & 511;
        g_wmod[(((size_t)b * NTAP + tap) * CO + o) * CI + i] = swm[i * 9 + tap] * d;
    }
}

// ------------------------------ 2) gemm -----------------------------------
// C[g][o][n] = sum_i A[g][o][i] * X[b(g)][i][n]
// grid: (N/128=8, M/128=4, 72), block 256, tile 128x128x16, 8x8 microtile (f32x2)
#define BM 128
#define BN 128
#define BK 16
#define ASTR (BM + 4)   // 132 floats; 132*4B multiple of 16 -> float4-safe

__global__ void __launch_bounds__(256) gemm_kernel(const float* __restrict__ x) {
    const int g = blockIdx.z;             // b*9 + tap
    const int b = g / 9;
    const float* A  = g_wmod + (size_t)g * CO * CI;          // [512][512] row-major
    const float* Bm = x      + (size_t)b * CI * HW;          // [512][1024] row-major
    float*       C  = g_ytap + (size_t)g * CO * HW;

    const int m0 = blockIdx.y * BM;
    const int n0 = blockIdx.x * BN;

    __shared__ float As[2][BK][ASTR];   // transposed: As[k][m]
    __shared__ float Bs[2][BK][BN];     // Bs[k][n]

    const int tid = threadIdx.x;
    const int a_r0 = tid >> 2;          // 0..63
    const int a_c4 = tid & 3;           // 0..3  (k float4 group)
    const int b_r0 = tid >> 5;          // 0..7
    const int b_c  = tid & 31;          // 0..31 (n float4 group)

    float4 ra[2], rb[2];

    auto loadA = [&](int kt) {
        #pragma unroll
        for (int r = 0; r < 2; r++) {
            int row = a_r0 + r * 64;
            ra[r] = *(const float4*)(A + (size_t)(m0 + row) * CI + kt * BK + a_c4 * 4);
        }
    };
    auto loadB = [&](int kt) {
        #pragma unroll
        for (int r = 0; r < 2; r++) {
            int row = b_r0 + r * 8;
            rb[r] = *(const float4*)(Bm + (size_t)(kt * BK + row) * HW + n0 + b_c * 4);
        }
    };
    auto storeA = [&](int buf) {
        #pragma unroll
        for (int r = 0; r < 2; r++) {
            int row = a_r0 + r * 64;
            As[buf][a_c4 * 4 + 0][row] = ra[r].x;
            As[buf][a_c4 * 4 + 1][row] = ra[r].y;
            As[buf][a_c4 * 4 + 2][row] = ra[r].z;
            As[buf][a_c4 * 4 + 3][row] = ra[r].w;
        }
    };
    auto storeB = [&](int buf) {
        #pragma unroll
        for (int r = 0; r < 2; r++) {
            int row = b_r0 + r * 8;
            *(float4*)&Bs[buf][row][b_c * 4] = rb[r];
        }
    };

    loadA(0); loadB(0);
    storeA(0); storeB(0);
    __syncthreads();

    unsigned long long acc[8][4];
    #pragma unroll
    for (int i = 0; i < 8; i++)
        #pragma unroll
        for (int j = 0; j < 4; j++) acc[i][j] = 0ull;

    const int ty = tid >> 4, tx = tid & 15;
    const int ry = ty * 4;      // rows ry..ry+3 and ry+64..ry+67
    const int cx = tx * 4;      // cols cx..cx+3 and cx+64..cx+67

    const int KT = CI / BK;     // 32
    for (int kt = 0; kt < KT; kt++) {
        const int cur = kt & 1;
        if (kt < KT - 1) { loadA(kt + 1); loadB(kt + 1); }

        #pragma unroll
        for (int k = 0; k < BK; k++) {
            float4 a0  = *(const float4*)&As[cur][k][ry];
            float4 a1  = *(const float4*)&As[cur][k][ry + 64];
            float4 b0f = *(const float4*)&Bs[cur][k][cx];
            float4 b1f = *(const float4*)&Bs[cur][k][cx + 64];

            unsigned long long bp[4] = {
                pk2(b0f.x, b0f.y), pk2(b0f.z, b0f.w),
                pk2(b1f.x, b1f.y), pk2(b1f.z, b1f.w)
            };
            float av[8] = { a0.x, a0.y, a0.z, a0.w, a1.x, a1.y, a1.z, a1.w };

            #pragma unroll
            for (int i = 0; i < 8; i++) {
                unsigned long long ap = pk2(av[i], av[i]);
                fma2(acc[i][0], ap, bp[0]);
                fma2(acc[i][1], ap, bp[1]);
                fma2(acc[i][2], ap, bp[2]);
                fma2(acc[i][3], ap, bp[3]);
            }
        }

        if (kt < KT - 1) {
            const int nxt = cur ^ 1;
            storeA(nxt); storeB(nxt);
            __syncthreads();
        }
    }

    // epilogue
    #pragma unroll
    for (int i = 0; i < 8; i++) {
        int row = m0 + ((i < 4) ? (ry + i) : (ry + 60 + i));
        float2 c0 = unpk2(acc[i][0]);
        float2 c1 = unpk2(acc[i][1]);
        float2 c2 = unpk2(acc[i][2]);
        float2 c3 = unpk2(acc[i][3]);
        float4 v0 = make_float4(c0.x, c0.y, c1.x, c1.y);
        float4 v1 = make_float4(c2.x, c2.y, c3.x, c3.y);
        *(float4*)(C + (size_t)row * HW + n0 + cx)      = v0;
        *(float4*)(C + (size_t)row * HW + n0 + cx + 64) = v1;
    }
}

// ------------------------------ 3) fir -------------------------------------
// grid: Bsz*CO = 4096, block 256. Each block: one (b,o), 64x64 outputs.
__global__ void __launch_bounds__(256) fir_kernel(float* __restrict__ out) {
    const int bo = blockIdx.x;
    const int b = bo >> 9, o = bo & 511;

    __shared__ float sY[NTAP][34][34];  // 41.6 KB, halo-padded tap planes

    const float* yb = g_ytap + ((size_t)b * NTAP * CO + o) * HW;
    const size_t plane = (size_t)CO * HW;  // stride between taps

    for (int idx = threadIdx.x; idx < NTAP * 34 * 34; idx += 256) {
        int tap = idx / 1156;
        int r = idx - tap * 1156;
        int hh = r / 34, ww = r - hh * 34;
        int h = hh - 1, wq = ww - 1;
        float v = 0.f;
        if ((unsigned)h < 32u && (unsigned)wq < 32u)
            v = yb[(size_t)tap * plane + h * 32 + wq];
        sY[tap][hh][ww] = v;
    }
    __syncthreads();

    // c1[e][dh][kh]  (dh index: 0 -> d=-1, 1 -> d=0, 2 -> d=+1)
    const float c1t[2][3][3] = {
        { {0.00f, 0.25f, 0.75f}, {0.75f, 0.75f, 0.25f}, {0.25f, 0.00f, 0.00f} },
        { {0.00f, 0.00f, 0.25f}, {0.25f, 0.75f, 0.75f}, {0.75f, 0.25f, 0.00f} }
    };

    float* ob = out + ((size_t)b * CO + o) * 4096;

    #pragma unroll
    for (int j = 0; j < 4; j++) {
        int pos = threadIdx.x + j * 256;   // 0..1023
        int P = pos >> 5, Q = pos & 31;

        float a00 = 0.f, a01 = 0.f, a10 = 0.f, a11 = 0.f;

        #pragma unroll
        for (int dh = 0; dh < 3; dh++)
            #pragma unroll
            for (int kh = 0; kh < 3; kh++) {
                const float ch0 = c1t[0][dh][kh];
                const float ch1 = c1t[1][dh][kh];
                if (ch0 == 0.f && ch1 == 0.f) continue;
                #pragma unroll
                for (int dw = 0; dw < 3; dw++)
                    #pragma unroll
                    for (int kw = 0; kw < 3; kw++) {
                        const float cw0 = c1t[0][dw][kw];
                        const float cw1 = c1t[1][dw][kw];
                        if (cw0 == 0.f && cw1 == 0.f) continue;
                        float v = sY[kh * 3 + kw][P + dh][Q + dw];
                        a00 += (ch0 * cw0) * v;
                        a01 += (ch0 * cw1) * v;
                        a10 += (ch1 * cw0) * v;
                        a11 += (ch1 * cw1) * v;
                    }
            }

        float2 r0 = make_float2(a00, a01);
        float2 r1 = make_float2(a10, a11);
        *(float2*)(ob + (size_t)(2 * P)     * 64 + 2 * Q) = r0;
        *(float2*)(ob + (size_t)(2 * P + 1) * 64 + 2 * Q) = r1;
    }
}

// ------------------------------ launch -------------------------------------
extern "C" void kernel_launch(void* const* d_in, const int* in_sizes, int n_in,
                              void* d_out, int out_size) {
    const float* x      = (const float*)d_in[0];  // [8,512,32,32]
    const float* styles = (const float*)d_in[1];  // [8,512]
    const float* w      = (const float*)d_in[2];  // [512,512,3,3]
    float* out = (float*)d_out;                   // [8,512,64,64]
    (void)in_sizes; (void)n_in; (void)out_size;

    prep_kernel<<<dim3(CO, Bsz), 256>>>(w, styles);
    gemm_kernel<<<dim3(BN == 128 ? 8 : 8, 4, Bsz * NTAP), 256>>>(x);
    fir_kernel<<<Bsz * CO, 256>>>(out);
}

// round 2
// speedup vs baseline: 1.0054x; 1.0054x over previous
#include <cuda_runtime.h>
#include <cuda_bf16.h>
#include <cstdint>

// ---------------------------------------------------------------------------
// ModulatedConv (StyleGAN2 modconv + conv_transpose2d stride2 + 4x4 FIR)
// Decomposition:
//   1) prep:  wm = w*gain*(style+1); d = rsqrt(sum wm^2 + eps); Wmod = wm*d
//             stored as [b][tap][o][i]   (tap = kh*3+kw)
//   2) gemm:  Ytap[b][tap][o][h*32+w] = sum_i Wmod[b][tap][o][i] * x[b][i][h*32+w]
//             72 GEMMs of M=512, N=1024, K=512   (pure GEMM, no im2col)
//   3) fir:   y1[s,t] = sum_{kh,kw: s=2h+kh,t=2w+kw} Ytap[kh][kw][h][w]
//             y2[p,q] = sum_{u,v} f[u,v] y1[p-1+u,q-1+v]
//             collapsed via c1[e][d][kh] = f1[2d+kh-e+1]/4, f1={.25,.75,.75,.25}
// ---------------------------------------------------------------------------

#define Bsz   8
#define CI    512
#define CO    512
#define HW    1024   // 32*32
#define NTAP  9

// scratch (device globals; no runtime allocation allowed)
__device__ float g_wmod[(size_t)Bsz * NTAP * CO * CI];   // 75.5 MB
__device__ float g_ytap[(size_t)Bsz * NTAP * CO * HW];   // 151 MB

// ------------------------------ helpers -----------------------------------
__device__ __forceinline__ unsigned long long pk2(float x, float y) {
    unsigned long long r;
    asm("mov.b64 %0, {%1,%2};" : "=l"(r) : "f"(x), "f"(y));
    return r;
}
__device__ __forceinline__ float2 unpk2(unsigned long long v) {
    float2 r;
    asm("mov.b64 {%0,%1}, %2;" : "=f"(r.x), "=f"(r.y) : "l"(v));
    return r;
}
__device__ __forceinline__ void fma2(unsigned long long& d,
                                     unsigned long long a,
                                     unsigned long long b) {
    asm("fma.rn.f32x2 %0, %1, %2, %0;" : "+l"(d) : "l"(a), "l"(b));
}

// ------------------------------ 1) prep -----------------------------------
// grid: (CO, Bsz), block: 256
__global__ void __launch_bounds__(256) prep_kernel(const float* __restrict__ w,
                                                   const float* __restrict__ styles) {
    const int o = blockIdx.x;
    const int b = blockIdx.y;
    const float gain = 1.0f / 1536.0f;  // 1/sqrt(512*512*9)

    __shared__ float swm[CI * NTAP];    // 18 KB, [i][tap] order (matches w layout)
    __shared__ float red[8];
    __shared__ float s_d;

    const float* wo = w + (size_t)o * (CI * NTAP);
    const float* st = styles + (size_t)b * CI;

    float lsum = 0.f;
    for (int idx = threadIdx.x; idx < CI * NTAP; idx += 256) {
        int i = idx / 9;
        float v = wo[idx] * gain * (st[i] + 1.0f);
        swm[idx] = v;
        lsum += v * v;
    }
    // block reduce
    #pragma unroll
    for (int off = 16; off; off >>= 1)
        lsum += __shfl_down_sync(0xffffffffu, lsum, off);
    if ((threadIdx.x & 31) == 0) red[threadIdx.x >> 5] = lsum;
    __syncthreads();
    if (threadIdx.x == 0) {
        float t = 0.f;
        #pragma unroll
        for (int k = 0; k < 8; k++) t += red[k];
        s_d = rsqrtf(t + 1e-8f);
    }
    __syncthreads();
    const float d = s_d;

    // write [b][tap][o][i] with i contiguous (coalesced)
    for (int idx = threadIdx.x; idx < CI * NTAP; idx += 256) {
        int tap = idx >> 9;          // 0..8
        int i   = idx & 511;
        g_wmod[(((size_t)b * NTAP + tap) * CO + o) * CI + i] = swm[i * 9 + tap] * d;
    }
}

// ------------------------------ 2) gemm -----------------------------------
// C[g][o][n] = sum_i A[g][o][i] * X[b(g)][i][n]
// grid: (N/128=8, M/128=4, 72), block 256, tile 128x128x16, 8x8 microtile (f32x2)
#define BM 128
#define BN 128
#define BK 16
#define ASTR (BM + 4)   // 132 floats; 132*4B multiple of 16 -> float4-safe

__global__ void __launch_bounds__(256) gemm_kernel(const float* __restrict__ x) {
    const int g = blockIdx.z;             // b*9 + tap
    const int b = g / 9;
    const float* A  = g_wmod + (size_t)g * CO * CI;          // [512][512] row-major
    const float* Bm = x      + (size_t)b * CI * HW;          // [512][1024] row-major
    float*       C  = g_ytap + (size_t)g * CO * HW;

    const int m0 = blockIdx.y * BM;
    const int n0 = blockIdx.x * BN;

    __shared__ float As[2][BK][ASTR];   // transposed: As[k][m]
    __shared__ float Bs[2][BK][BN];     // Bs[k][n]

    const int tid = threadIdx.x;
    const int a_r0 = tid >> 2;          // 0..63
    const int a_c4 = tid & 3;           // 0..3  (k float4 group)
    const int b_r0 = tid >> 5;          // 0..7
    const int b_c  = tid & 31;          // 0..31 (n float4 group)

    float4 ra[2], rb[2];

    auto loadA = [&](int kt) {
        #pragma unroll
        for (int r = 0; r < 2; r++) {
            int row = a_r0 + r * 64;
            ra[r] = *(const float4*)(A + (size_t)(m0 + row) * CI + kt * BK + a_c4 * 4);
        }
    };
    auto loadB = [&](int kt) {
        #pragma unroll
        for (int r = 0; r < 2; r++) {
            int row = b_r0 + r * 8;
            rb[r] = *(const float4*)(Bm + (size_t)(kt * BK + row) * HW + n0 + b_c * 4);
        }
    };
    auto storeA = [&](int buf) {
        #pragma unroll
        for (int r = 0; r < 2; r++) {
            int row = a_r0 + r * 64;
            As[buf][a_c4 * 4 + 0][row] = ra[r].x;
            As[buf][a_c4 * 4 + 1][row] = ra[r].y;
            As[buf][a_c4 * 4 + 2][row] = ra[r].z;
            As[buf][a_c4 * 4 + 3][row] = ra[r].w;
        }
    };
    auto storeB = [&](int buf) {
        #pragma unroll
        for (int r = 0; r < 2; r++) {
            int row = b_r0 + r * 8;
            *(float4*)&Bs[buf][row][b_c * 4] = rb[r];
        }
    };

    loadA(0); loadB(0);
    storeA(0); storeB(0);
    __syncthreads();

    unsigned long long acc[8][4];
    #pragma unroll
    for (int i = 0; i < 8; i++)
        #pragma unroll
        for (int j = 0; j < 4; j++) acc[i][j] = 0ull;

    const int ty = tid >> 4, tx = tid & 15;
    const int ry = ty * 4;      // rows ry..ry+3 and ry+64..ry+67
    const int cx = tx * 4;      // cols cx..cx+3 and cx+64..cx+67

    const int KT = CI / BK;     // 32
    for (int kt = 0; kt < KT; kt++) {
        const int cur = kt & 1;
        if (kt < KT - 1) { loadA(kt + 1); loadB(kt + 1); }

        #pragma unroll
        for (int k = 0; k < BK; k++) {
            float4 a0  = *(const float4*)&As[cur][k][ry];
            float4 a1  = *(const float4*)&As[cur][k][ry + 64];
            float4 b0f = *(const float4*)&Bs[cur][k][cx];
            float4 b1f = *(const float4*)&Bs[cur][k][cx + 64];

            unsigned long long bp[4] = {
                pk2(b0f.x, b0f.y), pk2(b0f.z, b0f.w),
                pk2(b1f.x, b1f.y), pk2(b1f.z, b1f.w)
            };
            float av[8] = { a0.x, a0.y, a0.z, a0.w, a1.x, a1.y, a1.z, a1.w };

            #pragma unroll
            for (int i = 0; i < 8; i++) {
                unsigned long long ap = pk2(av[i], av[i]);
                fma2(acc[i][0], ap, bp[0]);
                fma2(acc[i][1], ap, bp[1]);
                fma2(acc[i][2], ap, bp[2]);
                fma2(acc[i][3], ap, bp[3]);
            }
        }

        if (kt < KT - 1) {
            const int nxt = cur ^ 1;
            storeA(nxt); storeB(nxt);
            __syncthreads();
        }
    }

    // epilogue
    #pragma unroll
    for (int i = 0; i < 8; i++) {
        int row = m0 + ((i < 4) ? (ry + i) : (ry + 60 + i));
        float2 c0 = unpk2(acc[i][0]);
        float2 c1 = unpk2(acc[i][1]);
        float2 c2 = unpk2(acc[i][2]);
        float2 c3 = unpk2(acc[i][3]);
        float4 v0 = make_float4(c0.x, c0.y, c1.x, c1.y);
        float4 v1 = make_float4(c2.x, c2.y, c3.x, c3.y);
        *(float4*)(C + (size_t)row * HW + n0 + cx)      = v0;
        *(float4*)(C + (size_t)row * HW + n0 + cx + 64) = v1;
    }
}

// ------------------------------ 3) fir -------------------------------------
// grid: Bsz*CO = 4096, block 256. Each block: one (b,o), 64x64 outputs.
__global__ void __launch_bounds__(256) fir_kernel(float* __restrict__ out) {
    const int bo = blockIdx.x;
    const int b = bo >> 9, o = bo & 511;

    __shared__ float sY[NTAP][34][34];  // 41.6 KB, halo-padded tap planes

    const float* yb = g_ytap + ((size_t)b * NTAP * CO + o) * HW;
    const size_t plane = (size_t)CO * HW;  // stride between taps

    for (int idx = threadIdx.x; idx < NTAP * 34 * 34; idx += 256) {
        int tap = idx / 1156;
        int r = idx - tap * 1156;
        int hh = r / 34, ww = r - hh * 34;
        int h = hh - 1, wq = ww - 1;
        float v = 0.f;
        if ((unsigned)h < 32u && (unsigned)wq < 32u)
            v = yb[(size_t)tap * plane + h * 32 + wq];
        sY[tap][hh][ww] = v;
    }
    __syncthreads();

    // c1[e][dh][kh]  (dh index: 0 -> d=-1, 1 -> d=0, 2 -> d=+1)
    const float c1t[2][3][3] = {
        { {0.00f, 0.25f, 0.75f}, {0.75f, 0.75f, 0.25f}, {0.25f, 0.00f, 0.00f} },
        { {0.00f, 0.00f, 0.25f}, {0.25f, 0.75f, 0.75f}, {0.75f, 0.25f, 0.00f} }
    };

    float* ob = out + ((size_t)b * CO + o) * 4096;

    #pragma unroll
    for (int j = 0; j < 4; j++) {
        int pos = threadIdx.x + j * 256;   // 0..1023
        int P = pos >> 5, Q = pos & 31;

        float a00 = 0.f, a01 = 0.f, a10 = 0.f, a11 = 0.f;

        #pragma unroll
        for (int dh = 0; dh < 3; dh++)
            #pragma unroll
            for (int kh = 0; kh < 3; kh++) {
                const float ch0 = c1t[0][dh][kh];
                const float ch1 = c1t[1][dh][kh];
                if (ch0 == 0.f && ch1 == 0.f) continue;
                #pragma unroll
                for (int dw = 0; dw < 3; dw++)
                    #pragma unroll
                    for (int kw = 0; kw < 3; kw++) {
                        const float cw0 = c1t[0][dw][kw];
                        const float cw1 = c1t[1][dw][kw];
                        if (cw0 == 0.f && cw1 == 0.f) continue;
                        float v = sY[kh * 3 + kw][P + dh][Q + dw];
                        a00 += (ch0 * cw0) * v;
                        a01 += (ch0 * cw1) * v;
                        a10 += (ch1 * cw0) * v;
                        a11 += (ch1 * cw1) * v;
                    }
            }

        float2 r0 = make_float2(a00, a01);
        float2 r1 = make_float2(a10, a11);
        *(float2*)(ob + (size_t)(2 * P)     * 64 + 2 * Q) = r0;
        *(float2*)(ob + (size_t)(2 * P + 1) * 64 + 2 * Q) = r1;
    }
}

// ------------------------------ launch -------------------------------------
extern "C" void kernel_launch(void* const* d_in, const int* in_sizes, int n_in,
                              void* d_out, int out_size) {
    const float* x      = (const float*)d_in[0];  // [8,512,32,32]
    const float* styles = (const float*)d_in[1];  // [8,512]
    const float* w      = (const float*)d_in[2];  // [512,512,3,3]
    float* out = (float*)d_out;                   // [8,512,64,64]
    (void)in_sizes; (void)n_in; (void)out_size;

    prep_kernel<<<dim3(CO, Bsz), 256>>>(w, styles);
    gemm_kernel<<<dim3(BN == 128 ? 8 : 8, 4, Bsz * NTAP), 256>>>(x);
    fir_kernel<<<Bsz * CO, 256>>>(out);
}

// round 4
// speedup vs baseline: 1.8633x; 1.8533x over previous
#include <cuda_runtime.h>
#include <cstdint>

#define Bsz   8
#define CI    512
#define CO    512
#define HW    1024
#define NTAP  9

__device__ float g_At[(size_t)NTAP * CO * CI];          // 9.4 MB  A' = w*gain (tf32 bits)
__device__ float g_Bx[(size_t)Bsz * CI * HW];           // 16.8 MB B' = x*(s+1) (tf32 bits)
__device__ float g_ytap[(size_t)Bsz * NTAP * CO * HW];  // 151 MB
__device__ float g_demod[Bsz * CO];

__device__ __forceinline__ uint32_t cvt_tf32(float x) {
    uint32_t u; asm("cvt.rn.tf32.f32 %0, %1;" : "=r"(u) : "f"(x)); return u;
}

// ---------------- prep W: A'[tap][o][i] = w[o][i][tap]*gain (tf32) + demod ----
// grid 512 (one per o), block 256
__global__ void __launch_bounds__(256) prep_w_kernel(const float* __restrict__ w,
                                                     const float* __restrict__ styles) {
    const int o = blockIdx.x, tid = threadIdx.x, wid = tid >> 5, lane = tid & 31;
    const float gain = 1.0f / 1536.0f;   // 1/sqrt(512*512*9)
    __shared__ float sW2[CI];
    const float* wo = w + (size_t)o * CI * NTAP;

    for (int i = tid; i < CI; i += 256) {
        float acc = 0.f;
        #pragma unroll
        for (int t = 0; t < 9; t++) {
            float v = wo[i * 9 + t] * gain;
            acc += v * v;
            *(uint32_t*)&g_At[((size_t)t * CO + o) * CI + i] = cvt_tf32(v);
        }
        sW2[i] = acc;
    }
    __syncthreads();
    const int b = wid;  // 8 warps = 8 batches
    float sum = 0.f;
    for (int i = lane; i < CI; i += 32) {
        float s = styles[b * CI + i] + 1.0f;
        sum += s * s * sW2[i];
    }
    #pragma unroll
    for (int o2 = 16; o2; o2 >>= 1) sum += __shfl_xor_sync(0xffffffffu, sum, o2);
    if (lane == 0) g_demod[b * CO + o] = rsqrtf(sum + 1e-8f);
}

// ---------------- prep X: B'[b][i][n] = x*(style+1) (tf32) --------------------
// grid 4096, block 256, float4 per thread
__global__ void __launch_bounds__(256) prep_x_kernel(const float* __restrict__ x,
                                                     const float* __restrict__ styles) {
    size_t idx = ((size_t)blockIdx.x * 256 + threadIdx.x);   // float4 index
    int bi = (int)(idx >> 8);            // (b*512+i)
    float s = styles[bi] + 1.0f;
    float4 v = *(const float4*)(x + idx * 4);
    uint4 r;
    r.x = cvt_tf32(v.x * s); r.y = cvt_tf32(v.y * s);
    r.z = cvt_tf32(v.z * s); r.w = cvt_tf32(v.w * s);
    *(uint4*)(g_Bx + idx * 4) = r;
}

// ---------------- GEMM: mma.sync m16n8k8 tf32 --------------------------------
// C[g][o][n] = sum_i A'[tap][o][i] * B'[b][i][n],  g = b*9+tap
// grid (8 n, 4 m, 72 g), 256 thr, block tile 128x128x16, warp tile 64x32
#define ASTR 20
#define BSTR 132

__global__ void __launch_bounds__(256, 2) gemm_kernel() {
    __shared__ float As[2][128 * ASTR];   // [m][k] stride 20
    __shared__ float Bs[2][16 * BSTR];    // [k][n] stride 132

    const int tid = threadIdx.x, wid = tid >> 5, lane = tid & 31;
    const int wm = wid >> 2, wn = wid & 3;          // 2 x 4 warps
    const int lq = lane >> 2, qq = lane & 3;

    const int n0 = blockIdx.x * 128, m0 = blockIdx.y * 128, gz = blockIdx.z;
    const int b = gz / 9, tap = gz - b * 9;

    const float* Ag = g_At + (size_t)tap * CO * CI;     // [512][512]
    const float* Bg = g_Bx + (size_t)b * CI * HW;       // [512][1024]
    float*       C  = g_ytap + (size_t)gz * CO * HW;

    const int a_r0 = tid >> 2, a_k4 = tid & 3;          // A: 64 rows x 4 k-quads
    const int b_r0 = tid >> 5, b_c4 = tid & 31;         // B: 8 rows x 32 n-quads

    float4 ra[2], rb[2];
    auto loadG = [&](int kt) {
        int k0 = kt * 16;
        ra[0] = *(const float4*)(Ag + (size_t)(m0 + a_r0) * CI + k0 + a_k4 * 4);
        ra[1] = *(const float4*)(Ag + (size_t)(m0 + a_r0 + 64) * CI + k0 + a_k4 * 4);
        rb[0] = *(const float4*)(Bg + (size_t)(k0 + b_r0) * HW + n0 + b_c4 * 4);
        rb[1] = *(const float4*)(Bg + (size_t)(k0 + b_r0 + 8) * HW + n0 + b_c4 * 4);
    };
    auto storeS = [&](int buf) {
        *(float4*)&As[buf][a_r0 * ASTR + a_k4 * 4]        = ra[0];
        *(float4*)&As[buf][(a_r0 + 64) * ASTR + a_k4 * 4] = ra[1];
        *(float4*)&Bs[buf][b_r0 * BSTR + b_c4 * 4]        = rb[0];
        *(float4*)&Bs[buf][(b_r0 + 8) * BSTR + b_c4 * 4]  = rb[1];
    };

    loadG(0); storeS(0); __syncthreads();

    float c[4][4][4];
    #pragma unroll
    for (int i = 0; i < 4; i++)
        #pragma unroll
        for (int j = 0; j < 4; j++)
            #pragma unroll
            for (int k = 0; k < 4; k++) c[i][j][k] = 0.f;

    const int mwarp = wm * 64, nwarp = wn * 32;

    for (int kt = 0; kt < 32; kt++) {
        const int cur = kt & 1;
        if (kt < 31) loadG(kt + 1);

        #pragma unroll
        for (int ks = 0; ks < 2; ks++) {
            const int kb = ks * 8 + qq;
            uint32_t a[4][4], bb[4][2];
            #pragma unroll
            for (int mt = 0; mt < 4; mt++) {
                const float* ap = &As[cur][(mwarp + mt * 16 + lq) * ASTR + kb];
                a[mt][0] = __float_as_uint(ap[0]);
                a[mt][1] = __float_as_uint(ap[8 * ASTR]);
                a[mt][2] = __float_as_uint(ap[4]);
                a[mt][3] = __float_as_uint(ap[8 * ASTR + 4]);
            }
            #pragma unroll
            for (int nt = 0; nt < 4; nt++) {
                const float* bp = &Bs[cur][kb * BSTR + nwarp + nt * 8 + lq];
                bb[nt][0] = __float_as_uint(bp[0]);
                bb[nt][1] = __float_as_uint(bp[4 * BSTR]);
            }
            #pragma unroll
            for (int mt = 0; mt < 4; mt++)
                #pragma unroll
                for (int nt = 0; nt < 4; nt++)
                    asm volatile(
                        "mma.sync.aligned.m16n8k8.row.col.f32.tf32.tf32.f32 "
                        "{%0,%1,%2,%3}, {%4,%5,%6,%7}, {%8,%9}, {%0,%1,%2,%3};"
                        : "+f"(c[mt][nt][0]), "+f"(c[mt][nt][1]),
                          "+f"(c[mt][nt][2]), "+f"(c[mt][nt][3])
                        : "r"(a[mt][0]), "r"(a[mt][1]), "r"(a[mt][2]), "r"(a[mt][3]),
                          "r"(bb[nt][0]), "r"(bb[nt][1]));
        }

        if (kt < 31) {
            __syncthreads();
            storeS(cur ^ 1);
            __syncthreads();
        }
    }

    #pragma unroll
    for (int mt = 0; mt < 4; mt++)
        #pragma unroll
        for (int nt = 0; nt < 4; nt++) {
            int row = m0 + mwarp + mt * 16 + lq;
            int col = n0 + nwarp + nt * 8 + 2 * qq;
            *(float2*)(C + (size_t)row * HW + col)       = make_float2(c[mt][nt][0], c[mt][nt][1]);
            *(float2*)(C + (size_t)(row + 8) * HW + col) = make_float2(c[mt][nt][2], c[mt][nt][3]);
        }
}

// ---------------- FIR + demod ------------------------------------------------
__global__ void __launch_bounds__(256) fir_kernel(float* __restrict__ out) {
    const int bo = blockIdx.x;
    const int b = bo >> 9, o = bo & 511;
    __shared__ float sY[NTAP][34][34];
    const float* yb = g_ytap + ((size_t)b * NTAP * CO + o) * HW;
    const size_t plane = (size_t)CO * HW;
    const float dd = g_demod[b * CO + o];

    for (int idx = threadIdx.x; idx < NTAP * 34 * 34; idx += 256) {
        int tap = idx / 1156, r2 = idx - tap * 1156;
        int hh = r2 / 34, ww = r2 - hh * 34;
        int h = hh - 1, wq = ww - 1;
        float v = 0.f;
        if ((unsigned)h < 32u && (unsigned)wq < 32u) v = yb[(size_t)tap * plane + h * 32 + wq];
        sY[tap][hh][ww] = v;
    }
    __syncthreads();

    const float c1t[2][3][3] = {
        { {0.00f, 0.25f, 0.75f}, {0.75f, 0.75f, 0.25f}, {0.25f, 0.00f, 0.00f} },
        { {0.00f, 0.00f, 0.25f}, {0.25f, 0.75f, 0.75f}, {0.75f, 0.25f, 0.00f} }
    };
    float* ob = out + ((size_t)b * CO + o) * 4096;

    #pragma unroll
    for (int j = 0; j < 4; j++) {
        int pos = threadIdx.x + j * 256;
        int P = pos >> 5, Q = pos & 31;
        float a00 = 0.f, a01 = 0.f, a10 = 0.f, a11 = 0.f;
        #pragma unroll
        for (int dh = 0; dh < 3; dh++)
            #pragma unroll
            for (int kh = 0; kh < 3; kh++) {
                const float ch0 = c1t[0][dh][kh], ch1 = c1t[1][dh][kh];
                if (ch0 == 0.f && ch1 == 0.f) continue;
                #pragma unroll
                for (int dw = 0; dw < 3; dw++)
                    #pragma unroll
                    for (int kw = 0; kw < 3; kw++) {
                        const float cw0 = c1t[0][dw][kw], cw1 = c1t[1][dw][kw];
                        if (cw0 == 0.f && cw1 == 0.f) continue;
                        float v = sY[kh * 3 + kw][P + dh][Q + dw];
                        a00 += (ch0 * cw0) * v;  a01 += (ch0 * cw1) * v;
                        a10 += (ch1 * cw0) * v;  a11 += (ch1 * cw1) * v;
                    }
            }
        *(float2*)(ob + (size_t)(2*P)   * 64 + 2*Q) = make_float2(a00 * dd, a01 * dd);
        *(float2*)(ob + (size_t)(2*P+1) * 64 + 2*Q) = make_float2(a10 * dd, a11 * dd);
    }
}

// ---------------- launch ------------------------------------------------------
extern "C" void kernel_launch(void* const* d_in, const int* in_sizes, int n_in,
                              void* d_out, int out_size) {
    const float* x      = (const float*)d_in[0];
    const float* styles = (const float*)d_in[1];
    const float* w      = (const float*)d_in[2];
    float* out = (float*)d_out;
    (void)in_sizes; (void)n_in; (void)out_size;

    prep_w_kernel<<<512, 256>>>(w, styles);
    prep_x_kernel<<<4096, 256>>>(x, styles);
    gemm_kernel<<<dim3(8, 4, 72), 256>>>();
    fir_kernel<<<Bsz * CO, 256>>>(out);
}

// round 5
// speedup vs baseline: 2.4629x; 1.3218x over previous
#include <cuda_runtime.h>
#include <cstdint>

#define Bsz   8
#define CI    512
#define CO    512
#define HW    1024
#define NTAP  9

__device__ float g_At[(size_t)NTAP * CO * CI];          // 9.4 MB  A' = w*gain (tf32)
__device__ float g_Bx[(size_t)Bsz * CI * HW];           // 16.8 MB B' = x*(s+1) (tf32)
__device__ float g_ytap[(size_t)Bsz * NTAP * CO * HW];  // 151 MB
__device__ float g_demod[Bsz * CO];

__device__ __forceinline__ uint32_t cvt_tf32(float x) {
    uint32_t u; asm("cvt.rn.tf32.f32 %0, %1;" : "=r"(u) : "f"(x)); return u;
}
__device__ __forceinline__ uint32_t smaddr(const void* p) {
    uint32_t a;
    asm("{ .reg .u64 t; cvta.to.shared.u64 t, %1; cvt.u32.u64 %0, t; }" : "=r"(a) : "l"(p));
    return a;
}
__device__ __forceinline__ void cp16(uint32_t dst, const void* src) {
    asm volatile("cp.async.cg.shared.global [%0], [%1], 16;" :: "r"(dst), "l"(src));
}
__device__ __forceinline__ void cp_commit() { asm volatile("cp.async.commit_group;"); }
template<int N> __device__ __forceinline__ void cp_wait() {
    asm volatile("cp.async.wait_group %0;" :: "n"(N));
}

// ---------------- prep W + demod: grid 512, block 256 ----------------
__global__ void __launch_bounds__(256) prep_w_kernel(const float* __restrict__ w,
                                                     const float* __restrict__ styles) {
    const int o = blockIdx.x, tid = threadIdx.x, wid = tid >> 5, lane = tid & 31;
    const float gain = 1.0f / 1536.0f;
    __shared__ float sW2[CI];
    const float* wo = w + (size_t)o * CI * NTAP;

    for (int i = tid; i < CI; i += 256) {
        float acc = 0.f;
        #pragma unroll
        for (int t = 0; t < 9; t++) {
            float v = wo[i * 9 + t] * gain;
            acc += v * v;
            *(uint32_t*)&g_At[((size_t)t * CO + o) * CI + i] = cvt_tf32(v);
        }
        sW2[i] = acc;
    }
    __syncthreads();
    const int b = wid;
    float sum = 0.f;
    for (int i = lane; i < CI; i += 32) {
        float s = styles[b * CI + i] + 1.0f;
        sum += s * s * sW2[i];
    }
    #pragma unroll
    for (int o2 = 16; o2; o2 >>= 1) sum += __shfl_xor_sync(0xffffffffu, sum, o2);
    if (lane == 0) g_demod[b * CO + o] = rsqrtf(sum + 1e-8f);
}

// ---------------- prep X: grid 4096, block 256 ----------------
__global__ void __launch_bounds__(256) prep_x_kernel(const float* __restrict__ x,
                                                     const float* __restrict__ styles) {
    size_t idx = ((size_t)blockIdx.x * 256 + threadIdx.x);
    int bi = (int)(idx >> 8);
    float s = styles[bi] + 1.0f;
    float4 v = *(const float4*)(x + idx * 4);
    uint4 r;
    r.x = cvt_tf32(v.x * s); r.y = cvt_tf32(v.y * s);
    r.z = cvt_tf32(v.z * s); r.w = cvt_tf32(v.w * s);
    *(uint4*)(g_Bx + idx * 4) = r;
}

// ---------------- GEMM: 128x256x16, 4-stage cp.async, warp 64x64 --------------
#define ASTR 20
#define BSTR 264
#define ASZ  (128 * ASTR)        // 2560 floats
#define BSZ  (16 * BSTR)         // 4224 floats
#define STGF (ASZ + BSZ)         // 6784 floats = 27136 B
#define NSTG 4
#define GEMM_SMEM (NSTG * STGF * 4)

__global__ void __launch_bounds__(256, 1) gemm_kernel() {
    extern __shared__ float sm[];

    const int tid = threadIdx.x, wid = tid >> 5, lane = tid & 31;
    const int wm = wid >> 2, wn = wid & 3;          // 2 x 4 warps -> 64x64 tiles
    const int lq = lane >> 2, qq = lane & 3;

    const int n0 = blockIdx.x * 256, m0 = blockIdx.y * 128, gz = blockIdx.z;
    const int b = gz / 9, tap = gz - b * 9;

    const float* Ag = g_At + (size_t)tap * CO * CI;
    const float* Bg = g_Bx + (size_t)b * CI * HW;
    float*       C  = g_ytap + (size_t)gz * CO * HW;

    const int a_r = tid >> 2, a_q = tid & 3;       // A: rows a_r, a_r+64; quad a_q
    const int b_r = tid >> 4, b_q = tid & 15;      // B: row b_r; quads b_q+16j

    auto load_stage = [&](int s, int kt) {
        const int k0 = kt * 16;
        float* A_s = sm + s * STGF;
        float* B_s = A_s + ASZ;
        cp16(smaddr(&A_s[a_r * ASTR + a_q * 4]),
             Ag + (size_t)(m0 + a_r) * CI + k0 + a_q * 4);
        cp16(smaddr(&A_s[(a_r + 64) * ASTR + a_q * 4]),
             Ag + (size_t)(m0 + a_r + 64) * CI + k0 + a_q * 4);
        #pragma unroll
        for (int j = 0; j < 4; j++) {
            int q = b_q + j * 16;
            cp16(smaddr(&B_s[b_r * BSTR + q * 4]),
                 Bg + (size_t)(k0 + b_r) * HW + n0 + q * 4);
        }
        cp_commit();
    };

    load_stage(0, 0); load_stage(1, 1); load_stage(2, 2);

    float c[4][8][4];
    #pragma unroll
    for (int i = 0; i < 4; i++)
        #pragma unroll
        for (int j = 0; j < 8; j++)
            #pragma unroll
            for (int k = 0; k < 4; k++) c[i][j][k] = 0.f;

    const int mwarp = wm * 64, nwarp = wn * 64;

    cp_wait<2>(); __syncthreads();

    for (int kt = 0; kt < 32; kt++) {
        const int buf = kt & 3;
        const float* As = sm + buf * STGF;
        const float* Bs = As + ASZ;

        #pragma unroll
        for (int ks = 0; ks < 2; ks++) {
            const int kb = ks * 8 + qq;
            uint32_t a[4][4], bb[8][2];
            #pragma unroll
            for (int mt = 0; mt < 4; mt++) {
                const float* ap = &As[(mwarp + mt * 16 + lq) * ASTR + kb];
                a[mt][0] = __float_as_uint(ap[0]);
                a[mt][1] = __float_as_uint(ap[8 * ASTR]);
                a[mt][2] = __float_as_uint(ap[4]);
                a[mt][3] = __float_as_uint(ap[8 * ASTR + 4]);
            }
            #pragma unroll
            for (int nt = 0; nt < 8; nt++) {
                const float* bp = &Bs[kb * BSTR + nwarp + nt * 8 + lq];
                bb[nt][0] = __float_as_uint(bp[0]);
                bb[nt][1] = __float_as_uint(bp[4 * BSTR]);
            }
            #pragma unroll
            for (int mt = 0; mt < 4; mt++)
                #pragma unroll
                for (int nt = 0; nt < 8; nt++)
                    asm volatile(
                        "mma.sync.aligned.m16n8k8.row.col.f32.tf32.tf32.f32 "
                        "{%0,%1,%2,%3}, {%4,%5,%6,%7}, {%8,%9}, {%0,%1,%2,%3};"
                        : "+f"(c[mt][nt][0]), "+f"(c[mt][nt][1]),
                          "+f"(c[mt][nt][2]), "+f"(c[mt][nt][3])
                        : "r"(a[mt][0]), "r"(a[mt][1]), "r"(a[mt][2]), "r"(a[mt][3]),
                          "r"(bb[nt][0]), "r"(bb[nt][1]));
        }

        if (kt + 3 < 32) load_stage((kt + 3) & 3, kt + 3);
        if (kt < 31) { cp_wait<2>(); __syncthreads(); }
    }

    #pragma unroll
    for (int mt = 0; mt < 4; mt++)
        #pragma unroll
        for (int nt = 0; nt < 8; nt++) {
            int row = m0 + mwarp + mt * 16 + lq;
            int col = n0 + nwarp + nt * 8 + 2 * qq;
            *(float2*)(C + (size_t)row * HW + col)       = make_float2(c[mt][nt][0], c[mt][nt][1]);
            *(float2*)(C + (size_t)(row + 8) * HW + col) = make_float2(c[mt][nt][2], c[mt][nt][3]);
        }
}

// ---------------- FIR + demod: grid 4096, block 256 ----------------
__global__ void __launch_bounds__(256) fir_kernel(float* __restrict__ out) {
    const int bo = blockIdx.x;
    const int b = bo >> 9, o = bo & 511;
    __shared__ float sY[NTAP][34][34];
    const float* yb = g_ytap + ((size_t)b * NTAP * CO + o) * HW;
    const size_t plane = (size_t)CO * HW;
    const float dd = g_demod[b * CO + o];

    // zero halo frame (corners overlap, fine)
    for (int e = threadIdx.x; e < NTAP * 136; e += 256) {
        int tap = e / 136, p = e - tap * 136;
        if      (p < 34)  sY[tap][0][p] = 0.f;
        else if (p < 68)  sY[tap][33][p - 34] = 0.f;
        else if (p < 102) sY[tap][p - 68][0] = 0.f;
        else              sY[tap][p - 102][33] = 0.f;
    }
    // interior: one float4 per thread per tap
    {
        const int h = threadIdx.x >> 3, q = threadIdx.x & 7;
        #pragma unroll
        for (int tap = 0; tap < NTAP; tap++) {
            float4 v = *(const float4*)(yb + (size_t)tap * plane + h * 32 + 4 * q);
            float* d = &sY[tap][h + 1][1 + 4 * q];
            d[0] = v.x; d[1] = v.y; d[2] = v.z; d[3] = v.w;
        }
    }
    __syncthreads();

    const float c1t[2][3][3] = {
        { {0.00f, 0.25f, 0.75f}, {0.75f, 0.75f, 0.25f}, {0.25f, 0.00f, 0.00f} },
        { {0.00f, 0.00f, 0.25f}, {0.25f, 0.75f, 0.75f}, {0.75f, 0.25f, 0.00f} }
    };
    float* ob = out + ((size_t)b * CO + o) * 4096;

    #pragma unroll
    for (int j = 0; j < 4; j++) {
        int pos = threadIdx.x + j * 256;
        int P = pos >> 5, Q = pos & 31;
        float a00 = 0.f, a01 = 0.f, a10 = 0.f, a11 = 0.f;
        #pragma unroll
        for (int dh = 0; dh < 3; dh++)
            #pragma unroll
            for (int kh = 0; kh < 3; kh++) {
                const float ch0 = c1t[0][dh][kh], ch1 = c1t[1][dh][kh];
                if (ch0 == 0.f && ch1 == 0.f) continue;
                #pragma unroll
                for (int dw = 0; dw < 3; dw++)
                    #pragma unroll
                    for (int kw = 0; kw < 3; kw++) {
                        const float cw0 = c1t[0][dw][kw], cw1 = c1t[1][dw][kw];
                        if (cw0 == 0.f && cw1 == 0.f) continue;
                        float v = sY[kh * 3 + kw][P + dh][Q + dw];
                        a00 += (ch0 * cw0) * v;  a01 += (ch0 * cw1) * v;
                        a10 += (ch1 * cw0) * v;  a11 += (ch1 * cw1) * v;
                    }
            }
        *(float2*)(ob + (size_t)(2*P)   * 64 + 2*Q) = make_float2(a00 * dd, a01 * dd);
        *(float2*)(ob + (size_t)(2*P+1) * 64 + 2*Q) = make_float2(a10 * dd, a11 * dd);
    }
}

// ---------------- launch ----------------
extern "C" void kernel_launch(void* const* d_in, const int* in_sizes, int n_in,
                              void* d_out, int out_size) {
    const float* x      = (const float*)d_in[0];
    const float* styles = (const float*)d_in[1];
    const float* w      = (const float*)d_in[2];
    float* out = (float*)d_out;
    (void)in_sizes; (void)n_in; (void)out_size;

    cudaFuncSetAttribute(gemm_kernel, cudaFuncAttributeMaxDynamicSharedMemorySize, GEMM_SMEM);

    prep_w_kernel<<<512, 256>>>(w, styles);
    prep_x_kernel<<<4096, 256>>>(x, styles);
    gemm_kernel<<<dim3(4, 4, 72), 256, GEMM_SMEM>>>();
    fir_kernel<<<Bsz * CO, 256>>>(out);
}

// round 6
// speedup vs baseline: 2.9061x; 1.1799x over previous
#include <cuda_runtime.h>
#include <cuda_fp16.h>
#include <cstdint>

#define Bsz   8
#define CI    512
#define CO    512
#define HW    1024
#define NTAP  9
#define ASCALE 1024.0f            // A pre-scale (keeps w*gain in fp16 normal range)

__device__ __half g_Ah[(size_t)NTAP * CO * CI];          // 4.7 MB  A'=w*gain*1024, [tap][o][i]
__device__ __half g_Bh[(size_t)Bsz * HW * CI];           // 8.4 MB  B'=x*(s+1),      [b][n][i]
__device__ float  g_ytap[(size_t)Bsz * NTAP * CO * HW];  // 151 MB (scaled by 1024)
__device__ float  g_demod[Bsz * CO];

__device__ __forceinline__ uint32_t smaddr(const void* p) {
    uint32_t a;
    asm("{ .reg .u64 t; cvta.to.shared.u64 t, %1; cvt.u32.u64 %0, t; }" : "=r"(a) : "l"(p));
    return a;
}
__device__ __forceinline__ void cp16(uint32_t dst, const void* src) {
    asm volatile("cp.async.cg.shared.global [%0], [%1], 16;" :: "r"(dst), "l"(src));
}
__device__ __forceinline__ void cp_commit() { asm volatile("cp.async.commit_group;"); }
template<int N> __device__ __forceinline__ void cp_wait() {
    asm volatile("cp.async.wait_group %0;" :: "n"(N));
}

// ---------------- prep W: A'[tap][o][i] = w[o][i][tap]*gain*1024 (fp16) + demod
// grid 512 (one per o), block 256
__global__ void __launch_bounds__(256) prep_w_kernel(const float* __restrict__ w,
                                                     const float* __restrict__ styles) {
    const int o = blockIdx.x, tid = threadIdx.x, wid = tid >> 5, lane = tid & 31;
    const float gain = 1.0f / 1536.0f;
    __shared__ float sW2[CI];
    const float* wo = w + (size_t)o * CI * NTAP;

    for (int i = tid; i < CI; i += 256) {
        float acc = 0.f;
        #pragma unroll
        for (int t = 0; t < 9; t++) {
            float v = wo[i * 9 + t] * gain;
            acc += v * v;
            g_Ah[((size_t)t * CO + o) * CI + i] = __float2half_rn(v * ASCALE);
        }
        sW2[i] = acc;
    }
    __syncthreads();
    const int b = wid;   // 8 warps = 8 batches
    float sum = 0.f;
    for (int i = lane; i < CI; i += 32) {
        float s = styles[b * CI + i] + 1.0f;
        sum += s * s * sW2[i];
    }
    #pragma unroll
    for (int o2 = 16; o2; o2 >>= 1) sum += __shfl_xor_sync(0xffffffffu, sum, o2);
    if (lane == 0) g_demod[b * CO + o] = rsqrtf(sum + 1e-8f);
}

// ---------------- prep X: B'[b][n][i] = x[b][i][n]*(s+1) (fp16, transposed) ----
// grid (b=8, it=8, nt=16), block 256: 64x64 tile transpose
__global__ void __launch_bounds__(256) prep_x_kernel(const float* __restrict__ x,
                                                     const float* __restrict__ styles) {
    const int b = blockIdx.x, it = blockIdx.y, nt = blockIdx.z;
    const int i0 = it * 64, n0 = nt * 64;
    __shared__ float sx[64][65];

    #pragma unroll
    for (int e = 0; e < 16; e++) {
        int idx = e * 256 + threadIdx.x;
        int ii = idx >> 6, nn = idx & 63;
        float s = styles[b * CI + i0 + ii] + 1.0f;
        sx[ii][nn] = x[((size_t)b * CI + i0 + ii) * HW + n0 + nn] * s;
    }
    __syncthreads();
    #pragma unroll
    for (int e = 0; e < 16; e++) {
        int idx = e * 256 + threadIdx.x;
        int nn = idx >> 6, ii = idx & 63;
        g_Bh[((size_t)b * HW + n0 + nn) * CI + i0 + ii] = __float2half_rn(sx[ii][nn]);
    }
}

// ---------------- GEMM: fp16 m16n8k16, tile 128x128x16, 4-stage, 2 CTA/SM -----
// C[g][o][n] = sum_i A'[tap][o][i] * B'[b][n][i],  g = b*9+tap
#define SA 24                      // smem K stride in halfs (conflict-free)
#define STG (128 * SA)             // halfs per operand per stage (3072)

__global__ void __launch_bounds__(256, 2) gemm_kernel() {
    __shared__ __half sm[4][2][STG];   // [stage][A/B][...] = 48 KB exactly

    const int tid = threadIdx.x, wid = tid >> 5, lane = tid & 31;
    const int lq = lane >> 2, qq = lane & 3;
    const int wm = wid >> 2, wn = wid & 3;       // 2x4 warps, warp tile 64x32
    const int mwarp = wm * 64, nwarp = wn * 32;

    const int n0 = blockIdx.x * 128, m0 = blockIdx.y * 128, gz = blockIdx.z;
    const int b = gz / 9, tap = gz - b * 9;

    const __half* Ag = g_Ah + (size_t)tap * CO * CI;
    const __half* Bg = g_Bh + (size_t)b * HW * CI;
    float*        C  = g_ytap + (size_t)gz * CO * HW;

    const int l_r = tid >> 1, l_h = tid & 1;     // 128 rows x 2 halves (16B each)

    auto load_stage = [&](int s, int kt) {
        const int k0 = kt * 16;
        cp16(smaddr(&sm[s][0][l_r * SA + l_h * 8]),
             Ag + (size_t)(m0 + l_r) * CI + k0 + l_h * 8);
        cp16(smaddr(&sm[s][1][l_r * SA + l_h * 8]),
             Bg + (size_t)(n0 + l_r) * CI + k0 + l_h * 8);
        cp_commit();
    };

    load_stage(0, 0); load_stage(1, 1); load_stage(2, 2);

    float c[4][4][4];
    #pragma unroll
    for (int i = 0; i < 4; i++)
        #pragma unroll
        for (int j = 0; j < 4; j++)
            #pragma unroll
            for (int k = 0; k < 4; k++) c[i][j][k] = 0.f;

    for (int kt = 0; kt < 32; kt++) {
        cp_wait<2>();
        __syncthreads();
        const __half* As = sm[kt & 3][0];
        const __half* Bs = sm[kt & 3][1];

        if (kt + 3 < 32) load_stage((kt + 3) & 3, kt + 3);

        uint32_t a[4][4], bb[4][2];
        #pragma unroll
        for (int mt = 0; mt < 4; mt++) {
            const __half* ap = &As[(mwarp + mt * 16 + lq) * SA + 2 * qq];
            a[mt][0] = *(const uint32_t*)(ap);
            a[mt][1] = *(const uint32_t*)(ap + 8 * SA);
            a[mt][2] = *(const uint32_t*)(ap + 8);
            a[mt][3] = *(const uint32_t*)(ap + 8 * SA + 8);
        }
        #pragma unroll
        for (int nt = 0; nt < 4; nt++) {
            const __half* bp = &Bs[(nwarp + nt * 8 + lq) * SA + 2 * qq];
            bb[nt][0] = *(const uint32_t*)(bp);
            bb[nt][1] = *(const uint32_t*)(bp + 8);
        }
        #pragma unroll
        for (int mt = 0; mt < 4; mt++)
            #pragma unroll
            for (int nt = 0; nt < 4; nt++)
                asm volatile(
                    "mma.sync.aligned.m16n8k16.row.col.f32.f16.f16.f32 "
                    "{%0,%1,%2,%3}, {%4,%5,%6,%7}, {%8,%9}, {%0,%1,%2,%3};"
                    : "+f"(c[mt][nt][0]), "+f"(c[mt][nt][1]),
                      "+f"(c[mt][nt][2]), "+f"(c[mt][nt][3])
                    : "r"(a[mt][0]), "r"(a[mt][1]), "r"(a[mt][2]), "r"(a[mt][3]),
                      "r"(bb[nt][0]), "r"(bb[nt][1]));
        __syncthreads();
    }

    #pragma unroll
    for (int mt = 0; mt < 4; mt++)
        #pragma unroll
        for (int nt = 0; nt < 4; nt++) {
            int row = m0 + mwarp + mt * 16 + lq;
            int col = n0 + nwarp + nt * 8 + 2 * qq;
            *(float2*)(C + (size_t)row * HW + col)       = make_float2(c[mt][nt][0], c[mt][nt][1]);
            *(float2*)(C + (size_t)(row + 8) * HW + col) = make_float2(c[mt][nt][2], c[mt][nt][3]);
        }
}

// ---------------- FIR + demod (dd absorbs 1/ASCALE) ----------------
__global__ void __launch_bounds__(256) fir_kernel(float* __restrict__ out) {
    const int bo = blockIdx.x;
    const int b = bo >> 9, o = bo & 511;
    __shared__ float sY[NTAP][34][34];
    const float* yb = g_ytap + ((size_t)b * NTAP * CO + o) * HW;
    const size_t plane = (size_t)CO * HW;
    const float dd = g_demod[b * CO + o] * (1.0f / ASCALE);

    for (int e = threadIdx.x; e < NTAP * 136; e += 256) {
        int tap = e / 136, p = e - tap * 136;
        if      (p < 34)  sY[tap][0][p] = 0.f;
        else if (p < 68)  sY[tap][33][p - 34] = 0.f;
        else if (p < 102) sY[tap][p - 68][0] = 0.f;
        else              sY[tap][p - 102][33] = 0.f;
    }
    {
        const int h = threadIdx.x >> 3, q = threadIdx.x & 7;
        #pragma unroll
        for (int tap = 0; tap < NTAP; tap++) {
            float4 v = *(const float4*)(yb + (size_t)tap * plane + h * 32 + 4 * q);
            float* d = &sY[tap][h + 1][1 + 4 * q];
            d[0] = v.x; d[1] = v.y; d[2] = v.z; d[3] = v.w;
        }
    }
    __syncthreads();

    const float c1t[2][3][3] = {
        { {0.00f, 0.25f, 0.75f}, {0.75f, 0.75f, 0.25f}, {0.25f, 0.00f, 0.00f} },
        { {0.00f, 0.00f, 0.25f}, {0.25f, 0.75f, 0.75f}, {0.75f, 0.25f, 0.00f} }
    };
    float* ob = out + ((size_t)b * CO + o) * 4096;

    #pragma unroll
    for (int j = 0; j < 4; j++) {
        int pos = threadIdx.x + j * 256;
        int P = pos >> 5, Q = pos & 31;
        float a00 = 0.f, a01 = 0.f, a10 = 0.f, a11 = 0.f;
        #pragma unroll
        for (int dh = 0; dh < 3; dh++)
            #pragma unroll
            for (int kh = 0; kh < 3; kh++) {
                const float ch0 = c1t[0][dh][kh], ch1 = c1t[1][dh][kh];
                if (ch0 == 0.f && ch1 == 0.f) continue;
                #pragma unroll
                for (int dw = 0; dw < 3; dw++)
                    #pragma unroll
                    for (int kw = 0; kw < 3; kw++) {
                        const float cw0 = c1t[0][dw][kw], cw1 = c1t[1][dw][kw];
                        if (cw0 == 0.f && cw1 == 0.f) continue;
                        float v = sY[kh * 3 + kw][P + dh][Q + dw];
                        a00 += (ch0 * cw0) * v;  a01 += (ch0 * cw1) * v;
                        a10 += (ch1 * cw0) * v;  a11 += (ch1 * cw1) * v;
                    }
            }
        *(float2*)(ob + (size_t)(2*P)   * 64 + 2*Q) = make_float2(a00 * dd, a01 * dd);
        *(float2*)(ob + (size_t)(2*P+1) * 64 + 2*Q) = make_float2(a10 * dd, a11 * dd);
    }
}

// ---------------- launch ----------------
extern "C" void kernel_launch(void* const* d_in, const int* in_sizes, int n_in,
                              void* d_out, int out_size) {
    const float* x      = (const float*)d_in[0];
    const float* styles = (const float*)d_in[1];
    const float* w      = (const float*)d_in[2];
    float* out = (float*)d_out;
    (void)in_sizes; (void)n_in; (void)out_size;

    prep_w_kernel<<<512, 256>>>(w, styles);
    prep_x_kernel<<<dim3(8, 8, 16), 256>>>(x, styles);
    gemm_kernel<<<dim3(8, 4, 72), 256>>>();
    fir_kernel<<<Bsz * CO, 256>>>(out);
}